// round 6
// baseline (speedup 1.0000x reference)
#include <cuda_runtime.h>
#include <cuda_fp16.h>
#include <cstdint>

// ---------------- problem dims ----------------
#define T_DIM 8192
#define D_DIM 1024
#define H_DIM 4096

// scratch (device globals: no allocation allowed)
__device__ __half g_h  [(size_t)T_DIM * H_DIM];   // 64 MB intermediate (fp16)
__device__ __half g_xh [(size_t)T_DIM * D_DIM];   // fp16 x
__device__ __half g_wfc[(size_t)H_DIM * D_DIM];   // fp16 W_fc
__device__ __half g_wpr[(size_t)D_DIM * H_DIM];   // fp16 W_proj

// ---------------- helpers ----------------
__device__ __forceinline__ uint32_t smem_u32(const void* p) {
    uint32_t a;
    asm("{ .reg .u64 t; cvta.to.shared.u64 t, %1; cvt.u32.u64 %0, t; }" : "=r"(a) : "l"(p));
    return a;
}
__device__ __forceinline__ uint32_t swz(uint32_t b) {   // SW128: XOR bits[6:4] with bits[9:7]
    return b ^ ((b >> 3) & 0x70u);
}
__device__ __forceinline__ void cp_async16(uint32_t saddr, const void* g) {
    asm volatile("cp.async.cg.shared.global [%0], [%1], 16;" :: "r"(saddr), "l"(g));
}
#define CP_COMMIT() asm volatile("cp.async.commit_group;" ::: "memory")
#define CP_WAIT1()  asm volatile("cp.async.wait_group 1;" ::: "memory")

#define LDSM_X4(r0, r1, r2, r3, addr) \
    asm volatile("ldmatrix.sync.aligned.m8n8.x4.shared.b16 {%0,%1,%2,%3}, [%4];" \
        : "=r"(r0), "=r"(r1), "=r"(r2), "=r"(r3) : "r"(addr))

// fp16 MMA, fp32 accumulate: D(16x8) += A(16x16) * B(16x8)
#define MMA_F16(c0, c1, c2, c3, a0, a1, a2, a3, b0, b1) \
    asm volatile("mma.sync.aligned.m16n8k16.row.col.f32.f16.f16.f32 " \
        "{%0,%1,%2,%3}, {%4,%5,%6,%7}, {%8,%9}, {%0,%1,%2,%3};" \
        : "+f"(c0), "+f"(c1), "+f"(c2), "+f"(c3) \
        : "r"(a0), "r"(a1), "r"(a2), "r"(a3), "r"(b0), "r"(b1))

// ---------------- GEMM config ----------------
static constexpr int BLK_M = 128;
static constexpr int BLK_N = 128;
static constexpr int BLK_K = 64;                 // fp16 elems -> 128 bytes per row
static constexpr int STAGES = 3;                 // 96KB -> 2 CTAs / SM
static constexpr int A_BYTES = BLK_M * BLK_K * 2;          // 16384
static constexpr int B_BYTES = BLK_N * BLK_K * 2;          // 16384
static constexpr int STAGE_BYTES = A_BYTES + B_BYTES;      // 32768
static constexpr int SMEM_TOTAL = STAGES * STAGE_BYTES;    // 98304

// load one 128x64 A tile + 128x64 B tile (fp16) into stage at sBase
__device__ __forceinline__ void load_tile(uint32_t sBase, const __half* __restrict__ gA,
                                          const __half* __restrict__ gB, int K, int kt, int tid)
{
    const int k0 = kt * BLK_K;
    #pragma unroll
    for (int i = 0; i < 4; ++i) {                  // A: 1024 x 16B chunks / 256 thr
        int chunk = tid + i * 256;
        int row = chunk >> 3, unit = chunk & 7;    // 8 x 16B units per 128B row
        uint32_t off = row * 128 + unit * 16;
        cp_async16(sBase + swz(off), gA + (size_t)row * K + k0 + unit * 8);
    }
    #pragma unroll
    for (int i = 0; i < 4; ++i) {                  // B
        int chunk = tid + i * 256;
        int row = chunk >> 3, unit = chunk & 7;
        uint32_t off = row * 128 + unit * 16;
        cp_async16(sBase + A_BYTES + swz(off), gB + (size_t)row * K + k0 + unit * 8);
    }
}

// load one s-step's fragments (A 32x16, B 64x16) into buffers
__device__ __forceinline__ void load_frags(uint32_t a[2][4], uint32_t b[4][4],
                                           uint32_t st, uint32_t aLin0, uint32_t bLin0,
                                           uint32_t add, uint32_t xmask)
{
    LDSM_X4(a[0][0], a[0][1], a[0][2], a[0][3], st + ((aLin0 + add) ^ xmask));
    LDSM_X4(a[1][0], a[1][1], a[1][2], a[1][3], st + ((aLin0 + 16 * 128 + add) ^ xmask));
    // jp * 2048 only touches bits >= 11, commutes with the SW128 XOR
    const uint32_t b0 = st + A_BYTES;
    LDSM_X4(b[0][0], b[0][1], b[0][2], b[0][3], b0 + ((bLin0 + add) ^ xmask));
    LDSM_X4(b[1][0], b[1][1], b[1][2], b[1][3], b0 + ((bLin0 + add) ^ xmask) + 2048);
    LDSM_X4(b[2][0], b[2][1], b[2][2], b[2][3], b0 + ((bLin0 + add) ^ xmask) + 4096);
    LDSM_X4(b[3][0], b[3][1], b[3][2], b[3][3], b0 + ((bLin0 + add) ^ xmask) + 6144);
}

// OUT16: write C as fp16 (GEMM1 -> h). Otherwise fp32.
template <bool RELU2, bool OUT16>
__global__ void __launch_bounds__(256, 2) gemm_f16_mma(
    const __half* __restrict__ A,   // [M, K] row-major (K contiguous)
    const __half* __restrict__ B,   // [N, K] row-major (K contiguous)
    void* __restrict__ Cv,          // [M, N]
    int K, int ldc)
{
    extern __shared__ char smem[];
    const uint32_t sb = smem_u32(smem);
    const int tid  = threadIdx.x;
    const int lane = tid & 31;
    const int warp = tid >> 5;
    const int wm = (warp & 3) * 32;        // warp grid 4x2, warp tile 32x64
    const int wn = (warp >> 2) * 64;

    const __half* gA = A + (size_t)blockIdx.x * BLK_M * K;
    const __half* gB = B + (size_t)blockIdx.y * BLK_N * K;
    const int KT = K / BLK_K;

    // prologue: 2 stages in flight
    load_tile(sb, gA, gB, K, 0, tid);
    CP_COMMIT();
    load_tile(sb + STAGE_BYTES, gA, gB, K, 1, tid);
    CP_COMMIT();

    // ldmatrix linear offsets (swizzle XOR applied per access)
    const uint32_t xmask = (uint32_t)(lane & 7) << 4;
    const uint32_t aLin0 = (uint32_t)(wm + (lane & 15)) * 128 + (uint32_t)(lane >> 4) * 16;
    const uint32_t bLin0 = (uint32_t)(wn + (lane & 15)) * 128 + (uint32_t)(lane >> 4) * 16;

    float c[2][8][4];
    #pragma unroll
    for (int mi = 0; mi < 2; ++mi)
        #pragma unroll
        for (int j = 0; j < 8; ++j)
            #pragma unroll
            for (int q = 0; q < 4; ++q) c[mi][j][q] = 0.0f;

    uint32_t fa[2][2][4], fb[2][4][4];   // double-buffered fragments

    int curSt = 0, pfSt = 2;
    for (int kt = 0; kt < KT; ++kt) {
        CP_WAIT1();
        __syncthreads();

        // prefetch k-tile kt+2 into the slot consumed at kt-1
        int nk = kt + 2;
        if (nk < KT) load_tile(sb + pfSt * STAGE_BYTES, gA, gB, K, nk, tid);
        CP_COMMIT();
        if (++pfSt == STAGES) pfSt = 0;

        const uint32_t st = sb + curSt * STAGE_BYTES;
        if (++curSt == STAGES) curSt = 0;

        // fragments for step 0
        load_frags(fa[0], fb[0], st, aLin0, bLin0, 0, xmask);

        #pragma unroll
        for (int s = 0; s < 4; ++s) {              // 4 x K=16 steps (32B each)
            const int cur = s & 1, nxt = cur ^ 1;
            if (s < 3)                              // prefetch next step's fragments
                load_frags(fa[nxt], fb[nxt], st, aLin0, bLin0, (s + 1) * 32, xmask);
            #pragma unroll
            for (int mi = 0; mi < 2; ++mi)
                #pragma unroll
                for (int jp = 0; jp < 4; ++jp) {
                    MMA_F16(c[mi][2 * jp][0], c[mi][2 * jp][1], c[mi][2 * jp][2], c[mi][2 * jp][3],
                            fa[cur][mi][0], fa[cur][mi][1], fa[cur][mi][2], fa[cur][mi][3],
                            fb[cur][jp][0], fb[cur][jp][2]);
                    MMA_F16(c[mi][2 * jp + 1][0], c[mi][2 * jp + 1][1], c[mi][2 * jp + 1][2], c[mi][2 * jp + 1][3],
                            fa[cur][mi][0], fa[cur][mi][1], fa[cur][mi][2], fa[cur][mi][3],
                            fb[cur][jp][1], fb[cur][jp][3]);
                }
        }
    }

    // epilogue
    const int row0 = blockIdx.x * BLK_M + wm + (lane >> 2);
    const int col0 = blockIdx.y * BLK_N + wn + (lane & 3) * 2;
    #pragma unroll
    for (int mi = 0; mi < 2; ++mi)
        #pragma unroll
        for (int rr = 0; rr < 2; ++rr) {
            const int row = row0 + mi * 16 + rr * 8;
            #pragma unroll
            for (int j = 0; j < 8; ++j) {
                float v0 = c[mi][j][rr * 2], v1 = c[mi][j][rr * 2 + 1];
                if (RELU2) {
                    v0 = fmaxf(v0, 0.0f); v0 *= v0;
                    v1 = fmaxf(v1, 0.0f); v1 *= v1;
                }
                if (OUT16) {
                    __half* base = (__half*)Cv + (size_t)row * ldc + col0;
                    __half2 hv = __floats2half2_rn(v0, v1);
                    *reinterpret_cast<__half2*>(base + j * 8) = hv;
                } else {
                    float* base = (float*)Cv + (size_t)row * ldc + col0;
                    *reinterpret_cast<float2*>(base + j * 8) = make_float2(v0, v1);
                }
            }
        }
}

// ---------------- fp32 -> fp16 RN pre-pass ----------------
__global__ void to_half_kernel(const float4* __restrict__ in, __half2* __restrict__ out, int n4)
{
    int i = blockIdx.x * blockDim.x + threadIdx.x;
    if (i >= n4) return;
    float4 v = in[i];
    out[2 * i]     = __floats2half2_rn(v.x, v.y);
    out[2 * i + 1] = __floats2half2_rn(v.z, v.w);
}

// ---------------- host side ----------------
extern "C" void kernel_launch(void* const* d_in, const int* in_sizes, int n_in,
                              void* d_out, int out_size)
{
    const float* x   = (const float*)d_in[0];  // [8192, 1024]
    const float* wfc = (const float*)d_in[1];  // [4096, 1024]
    const float* wpr = (const float*)d_in[2];  // [1024, 4096]
    float* out = (float*)d_out;                // [8192, 1024]

    __half *h, *xh, *wfch, *wprh;
    cudaGetSymbolAddress((void**)&h,    g_h);
    cudaGetSymbolAddress((void**)&xh,   g_xh);
    cudaGetSymbolAddress((void**)&wfch, g_wfc);
    cudaGetSymbolAddress((void**)&wprh, g_wpr);

    cudaFuncSetAttribute(gemm_f16_mma<true, true>,
                         cudaFuncAttributeMaxDynamicSharedMemorySize, SMEM_TOTAL);
    cudaFuncSetAttribute(gemm_f16_mma<false, false>,
                         cudaFuncAttributeMaxDynamicSharedMemorySize, SMEM_TOTAL);

    // fp32 -> fp16 (RN) pre-pass; fp16 mantissa == tf32 mantissa (11 bits effective)
    {
        int n4x = T_DIM * D_DIM / 4;
        int n4f = H_DIM * D_DIM / 4;
        int n4p = D_DIM * H_DIM / 4;
        to_half_kernel<<<(n4x + 255) / 256, 256>>>((const float4*)x,   (__half2*)xh,   n4x);
        to_half_kernel<<<(n4f + 255) / 256, 256>>>((const float4*)wfc, (__half2*)wfch, n4f);
        to_half_kernel<<<(n4p + 255) / 256, 256>>>((const float4*)wpr, (__half2*)wprh, n4p);
    }

    // GEMM1: h = relu(x @ Wfc^T)^2   [8192, 4096], K = 1024, out fp16
    gemm_f16_mma<true, true><<<dim3(T_DIM / BLK_M, H_DIM / BLK_N), 256, SMEM_TOTAL>>>(
        xh, wfch, h, D_DIM, H_DIM);

    // GEMM2: out = h @ Wpr^T         [8192, 1024], K = 4096, out fp32
    gemm_f16_mma<false, false><<<dim3(T_DIM / BLK_M, D_DIM / BLK_N), 256, SMEM_TOTAL>>>(
        h, wprh, out, H_DIM, D_DIM);
}